// round 1
// baseline (speedup 1.0000x reference)
#include <cuda_runtime.h>
#include <math.h>

#define T_LEN   8192
#define F_DIM   8
#define B_SZ    128
#define NLAGS   24
#define THREADS 256
#define CHUNK   (T_LEN / THREADS)   // 32
#define EPSF    1e-8f
#define NWARPS  (THREADS / 32)      // 8

__device__ float g_partials[B_SZ];

// padded smem index: avoids 32-way bank conflicts on 32-stride window loads
__device__ __forceinline__ int zi(int t) { return t + (t >> 5); }

__global__ __launch_bounds__(THREADS)
void autocorr_kernel(const float* __restrict__ input,
                     const float* __restrict__ lagw,
                     const float* __restrict__ seas) {
    __shared__ float zs[T_LEN + (T_LEN >> 5)];   // padded row buffer
    __shared__ float redA[2 * NWARPS];
    __shared__ float redB[2 * NWARPS];
    __shared__ float warp_sxy[NWARPS][NLAGS];
    __shared__ float coef[NLAGS];
    __shared__ float s_res[NLAGS];
    __shared__ float s_mean, s_inv, s_S, s_Q;

    const int b    = blockIdx.x;
    const int tid  = threadIdx.x;
    const int warp = tid >> 5;
    const int lane = tid & 31;
    const float* row = input + (size_t)b * T_LEN * F_DIM;

    // ---- pass 1: load stride-8 column, raw sum / sumsq ----
    float lsum = 0.f, lsq = 0.f;
    for (int t = tid; t < T_LEN; t += THREADS) {
        float v = __ldg(row + (size_t)t * F_DIM);
        zs[zi(t)] = v;
        lsum += v;
        lsq  += v * v;
    }
    #pragma unroll
    for (int o = 16; o > 0; o >>= 1) {
        lsum += __shfl_xor_sync(0xffffffffu, lsum, o);
        lsq  += __shfl_xor_sync(0xffffffffu, lsq,  o);
    }
    if (lane == 0) { redA[warp] = lsum; redA[NWARPS + warp] = lsq; }
    __syncthreads();

    if (tid == 0) {
        float S = 0.f, Q = 0.f;
        #pragma unroll
        for (int i = 0; i < NWARPS; i++) { S += redA[i]; Q += redA[NWARPS + i]; }
        float mean = S / (float)T_LEN;
        float var  = (Q - S * S / (float)T_LEN) / (float)(T_LEN - 1);
        float sd   = sqrtf(fmaxf(var, 0.f));
        s_mean = mean;
        s_inv  = 1.f / (sd + EPSF);
        // softmax(lag_weights) + seasonal additions
        float mx = lagw[0];
        for (int i = 1; i < NLAGS; i++) mx = fmaxf(mx, lagw[i]);
        float se = 0.f;
        for (int i = 0; i < NLAGS; i++) se += expf(lagw[i] - mx);
        float inv_se = 1.f / se;
        for (int i = 0; i < NLAGS; i++) coef[i] = expf(lagw[i] - mx) * inv_se;
        coef[11] += seas[0];   // lag 12
        coef[23] += seas[1];   // lag 24
    }
    __syncthreads();

    // ---- pass 2: normalize in place; accumulate sums of stored z ----
    const float mean = s_mean, inv = s_inv;
    float ls2 = 0.f, lq2 = 0.f;
    for (int t = tid; t < T_LEN; t += THREADS) {
        float z = (zs[zi(t)] - mean) * inv;
        zs[zi(t)] = z;
        ls2 += z;
        lq2 += z * z;
    }
    #pragma unroll
    for (int o = 16; o > 0; o >>= 1) {
        ls2 += __shfl_xor_sync(0xffffffffu, ls2, o);
        lq2 += __shfl_xor_sync(0xffffffffu, lq2, o);
    }
    if (lane == 0) { redB[warp] = ls2; redB[NWARPS + warp] = lq2; }
    __syncthreads();   // also fences zs normalization for all threads
    if (tid == 0) {
        float S = 0.f, Q = 0.f;
        #pragma unroll
        for (int i = 0; i < NWARPS; i++) { S += redB[i]; Q += redB[NWARPS + i]; }
        s_S = S; s_Q = Q;
    }

    // ---- per-thread register window: 32 own + 24 lookahead ----
    float w[CHUNK + NLAGS];
    const int i0 = tid * CHUNK;
    #pragma unroll
    for (int j = 0; j < CHUNK + NLAGS; j++) {
        int idx = i0 + j;
        w[j] = (idx < T_LEN) ? zs[zi(idx)] : 0.f;   // zero-pad kills invalid products
    }
    float acc[NLAGS];
    #pragma unroll
    for (int l = 0; l < NLAGS; l++) acc[l] = 0.f;
    #pragma unroll
    for (int j = 0; j < CHUNK; j++) {
        #pragma unroll
        for (int l = 0; l < NLAGS; l++)
            acc[l] = fmaf(w[j], w[j + l + 1], acc[l]);
    }

    // ---- reduce Sxy per lag: warp shuffle -> smem -> 24 threads finish ----
    #pragma unroll
    for (int l = 0; l < NLAGS; l++) {
        float v = acc[l];
        #pragma unroll
        for (int o = 16; o > 0; o >>= 1)
            v += __shfl_xor_sync(0xffffffffu, v, o);
        if (lane == 0) warp_sxy[warp][l] = v;
    }
    __syncthreads();   // fences warp_sxy, s_S, s_Q

    if (tid < NLAGS) {
        const int l   = tid;
        const int lag = l + 1;
        float sxy = 0.f;
        #pragma unroll
        for (int wi = 0; wi < NWARPS; wi++) sxy += warp_sxy[wi][l];

        // head/tail partial sums (<=24 elements each)
        float hs = 0.f, hq = 0.f, ts = 0.f, tq = 0.f;
        for (int t = 0; t < lag; t++)           { float v = zs[zi(t)]; hs += v; hq += v * v; }
        for (int t = T_LEN - lag; t < T_LEN; t++){ float v = zs[zi(t)]; ts += v; tq += v * v; }

        const float S = s_S, Q = s_Q;
        const float Sx  = S - ts,  Sy  = S - hs;
        const float Sxx = Q - tq,  Syy = Q - hq;
        const float n   = (float)(T_LEN - lag);

        float num = sxy - Sx * Sy / n;
        float vx  = Sxx - Sx * Sx / n;
        float vy  = Syy - Sy * Sy / n;
        float r   = num / (sqrtf(fmaxf(vx, 0.f)) * sqrtf(fmaxf(vy, 0.f)));
        r = fminf(1.f, fmaxf(-1.f, r));
        s_res[l] = r * coef[l];
    }
    __syncthreads();

    if (tid == 0) {
        float acc_b = 0.f;
        #pragma unroll
        for (int l = 0; l < NLAGS; l++) acc_b += s_res[l];
        g_partials[b] = acc_b;
    }
}

__global__ void final_reduce_kernel(float* __restrict__ out) {
    __shared__ float wsum[4];
    int tid = threadIdx.x;
    float v = (tid < B_SZ) ? g_partials[tid] : 0.f;
    #pragma unroll
    for (int o = 16; o > 0; o >>= 1)
        v += __shfl_xor_sync(0xffffffffu, v, o);
    if ((tid & 31) == 0) wsum[tid >> 5] = v;
    __syncthreads();
    if (tid == 0)
        out[0] = (wsum[0] + wsum[1] + wsum[2] + wsum[3]) * (1.f / (float)B_SZ);
}

extern "C" void kernel_launch(void* const* d_in, const int* in_sizes, int n_in,
                              void* d_out, int out_size) {
    const float* input = (const float*)d_in[0];   // input_sequence (128,8192,8)
    // d_in[1] = hidden_states — intentionally unused (never referenced by the math)
    const float* lagw  = (const float*)d_in[2];   // lag_weights (24,)
    const float* seas  = (const float*)d_in[3];   // seasonal_importance (2,)
    float* out = (float*)d_out;

    autocorr_kernel<<<B_SZ, THREADS>>>(input, lagw, seas);
    final_reduce_kernel<<<1, 128>>>(out);
}